// round 12
// baseline (speedup 1.0000x reference)
#include <cuda_runtime.h>
#include <cstdint>

// SimpleCodebook VQ, R12 (= R11 resubmitted after infra failure):
// int8 IMMA approx pass with R4-geometry deep MMA windows (128x256 CTA tile,
// 64x64 warp tile, 32 IMMA per fragment batch) + exact fp64 rescore of
// ambiguous rows (DELTA=8).

#define NQ 8192
#define NC 8192
#define DD 512
#define BMT 128             // CTA tile M
#define BNT 256             // CTA tile N
#define BK  128             // K chunk (int8) -> 128B rows
#define NKC (DD / BK)       // 4
#define NGRP (NC / 64)      // 128 candidate groups per row (64 cols each)
#define DELTA 8.0f

#define NSTG 3
#define STG_BYTES 49152     // A(16K) + B(32K)
#define OFF_ESQ 0           // 256 floats
#define OFF_AE  1024        // 256 floats
#define OFF_AX  2048        // 128 floats
#define OFF_RED 2560        // 4 arrays x 128x4 x 4B = 8KB
#define OFF_STG 10752
#define SMEM_TOTAL (OFF_STG + NSTG * STG_BYTES)   // 158208 -> 1 CTA/SM

// ---- device global scratch ----
__device__ uint8_t g_Xq[NQ * DD];
__device__ uint8_t g_Eq[NC * DD];
__device__ float   g_ax[NQ];       // 2 * max|x_row| / 127
__device__ float   g_ae[NC];       // max|e_row| / 127
__device__ float   g_esq[NC];
__device__ float4  g_cand[NGRP * NQ];   // (v1, idx1_bits, v2, idx2_bits)

static __device__ __forceinline__ uint32_t smem_u32(const void* p) {
    uint32_t a;
    asm("{ .reg .u64 t; cvta.to.shared.u64 t, %1; cvt.u32.u64 %0, t; }" : "=r"(a) : "l"(p));
    return a;
}
static __device__ __forceinline__ uint32_t swz(uint32_t o) { return o ^ ((o >> 3) & 0x70); }

static __device__ __forceinline__ void cp16(uint32_t dst, const void* src) {
    asm volatile("cp.async.cg.shared.global [%0], [%1], 16;" :: "r"(dst), "l"(src) : "memory");
}
#define CP_COMMIT() asm volatile("cp.async.commit_group;" ::: "memory")
#define CP_WAIT0()  asm volatile("cp.async.wait_group 0;" ::: "memory")
#define CP_WAIT1()  asm volatile("cp.async.wait_group 1;" ::: "memory")

static __device__ __forceinline__ void ldsm_x4(uint32_t* r, uint32_t addr) {
    asm volatile("ldmatrix.sync.aligned.m8n8.x4.shared.b16 {%0,%1,%2,%3}, [%4];"
                 : "=r"(r[0]), "=r"(r[1]), "=r"(r[2]), "=r"(r[3]) : "r"(addr));
}
static __device__ __forceinline__ void imma(int* c, const uint32_t* a, const uint32_t* b) {
    asm volatile(
        "mma.sync.aligned.m16n8k32.row.col.s32.s8.s8.s32 "
        "{%0,%1,%2,%3}, {%4,%5,%6,%7}, {%8,%9}, {%0,%1,%2,%3};"
        : "+r"(c[0]), "+r"(c[1]), "+r"(c[2]), "+r"(c[3])
        : "r"(a[0]), "r"(a[1]), "r"(a[2]), "r"(a[3]), "r"(b[0]), "r"(b[1]));
}

static __device__ __forceinline__ int q8(float v, float inv) {
    int q = __float2int_rn(v * inv);
    return max(-127, min(127, q));
}

// ---------------------------------------------------------------------------
// Kernel 1: per-row quantize X (x2 folded into ax) and E; esq = ||e||^2
// ---------------------------------------------------------------------------
__global__ void convert_kernel(const float* __restrict__ X, const float* __restrict__ E) {
    int row = blockIdx.x;
    int t = threadIdx.x;                     // 128
    size_t base = (size_t)row * DD + t * 4;
    __shared__ float wmx[4], wme[4], wsq[4];
    __shared__ float s_ix, s_ie;

    float4 vx = *reinterpret_cast<const float4*>(X + base);
    float4 ve = *reinterpret_cast<const float4*>(E + base);

    float mx = fmaxf(fmaxf(fabsf(vx.x), fabsf(vx.y)), fmaxf(fabsf(vx.z), fabsf(vx.w)));
    float me = fmaxf(fmaxf(fabsf(ve.x), fabsf(ve.y)), fmaxf(fabsf(ve.z), fabsf(ve.w)));
    float sq = ve.x * ve.x + ve.y * ve.y + ve.z * ve.z + ve.w * ve.w;
    #pragma unroll
    for (int o = 16; o; o >>= 1) {
        mx = fmaxf(mx, __shfl_xor_sync(0xFFFFFFFFu, mx, o));
        me = fmaxf(me, __shfl_xor_sync(0xFFFFFFFFu, me, o));
        sq += __shfl_down_sync(0xFFFFFFFFu, sq, o);
    }
    if ((t & 31) == 0) { wmx[t >> 5] = mx; wme[t >> 5] = me; wsq[t >> 5] = sq; }
    __syncthreads();
    if (t == 0) {
        float Mx = fmaxf(fmaxf(wmx[0], wmx[1]), fmaxf(wmx[2], wmx[3]));
        float Me = fmaxf(fmaxf(wme[0], wme[1]), fmaxf(wme[2], wme[3]));
        Mx = fmaxf(Mx, 1e-20f);
        Me = fmaxf(Me, 1e-20f);
        g_ax[row] = 2.0f * Mx / 127.0f;
        g_ae[row] = Me / 127.0f;
        g_esq[row] = wsq[0] + wsq[1] + wsq[2] + wsq[3];
        s_ix = 127.0f / Mx;
        s_ie = 127.0f / Me;
    }
    __syncthreads();
    float ix = s_ix, ie = s_ie;

    uint32_t px = (uint32_t)(q8(vx.x, ix) & 0xFF)
                | ((uint32_t)(q8(vx.y, ix) & 0xFF) << 8)
                | ((uint32_t)(q8(vx.z, ix) & 0xFF) << 16)
                | ((uint32_t)(q8(vx.w, ix) & 0xFF) << 24);
    uint32_t pe = (uint32_t)(q8(ve.x, ie) & 0xFF)
                | ((uint32_t)(q8(ve.y, ie) & 0xFF) << 8)
                | ((uint32_t)(q8(ve.z, ie) & 0xFF) << 16)
                | ((uint32_t)(q8(ve.w, ie) & 0xFF) << 24);
    *reinterpret_cast<uint32_t*>(g_Xq + base) = px;
    *reinterpret_cast<uint32_t*>(g_Eq + base) = pe;
}

// ---------------------------------------------------------------------------
// Kernel 2: IMMA GEMM + top-2 per (row, 64-col group). grid (64,32), 256 thr.
// ---------------------------------------------------------------------------
static __device__ __forceinline__ void load_stage(uint32_t sb, int s, int kc,
                                                  int m0, int cb0, int tid) {
    uint32_t stg = sb + OFF_STG + s * STG_BYTES;
    // A: 128 rows x 128B
    #pragma unroll
    for (int i = 0; i < 4; i++) {
        int cid = tid + i * 256;              // 0..1023
        int row = cid >> 3;
        int c16 = cid & 7;
        const uint8_t* src = g_Xq + (size_t)(m0 + row) * DD + kc * BK + c16 * 16;
        cp16(stg + swz((uint32_t)(row * 128 + c16 * 16)), src);
    }
    // B: 256 rows x 128B
    #pragma unroll
    for (int i = 0; i < 8; i++) {
        int cid = tid + i * 256;              // 0..2047
        int row = cid >> 3;
        int c16 = cid & 7;
        const uint8_t* src = g_Eq + (size_t)(cb0 + row) * DD + kc * BK + c16 * 16;
        cp16(stg + 16384 + swz((uint32_t)(row * 128 + c16 * 16)), src);
    }
    CP_COMMIT();
}

static __device__ __forceinline__ void upd2(float v, int i, float& v1, int& i1,
                                            float& v2, int& i2) {
    if (v > v1 || (v == v1 && i < i1)) {
        v2 = v1; i2 = i1; v1 = v; i1 = i;
    } else if (v > v2 || (v == v2 && i < i2)) {
        v2 = v; i2 = i;
    }
}

__global__ __launch_bounds__(256, 1)
void vq_mma_kernel() {
    extern __shared__ char smem[];
    const uint32_t sb = smem_u32(smem);
    const int tid = threadIdx.x;
    const int lane = tid & 31;
    const int wid = tid >> 5;
    const int warp_m = wid >> 2;         // 0..1  (64 rows each)
    const int warp_n = wid & 3;          // 0..3  (64 cols each)
    const int m0 = blockIdx.x * BMT;
    const int cb0 = blockIdx.y * BNT;

    float* ses = reinterpret_cast<float*>(smem + OFF_ESQ);
    float* sae = reinterpret_cast<float*>(smem + OFF_AE);
    float* sax = reinterpret_cast<float*>(smem + OFF_AX);
    ses[tid] = g_esq[cb0 + tid];
    sae[tid] = g_ae[cb0 + tid];
    if (tid < BMT) sax[tid] = g_ax[m0 + tid];

    int acc[4][8][4];
    #pragma unroll
    for (int mf = 0; mf < 4; mf++)
        #pragma unroll
        for (int nf = 0; nf < 8; nf++)
            #pragma unroll
            for (int c = 0; c < 4; c++) acc[mf][nf][c] = 0;

    // hoisted swizzle: addr = stg + base + (k ^ m), m = ((row*128)>>3)&0x70
    const uint32_t a_row = (uint32_t)(warp_m * 64 + (lane & 15));
    const uint32_t a_kb  = (uint32_t)((lane >> 4) * 16);
    const uint32_t b_row = (uint32_t)(warp_n * 64 + (lane >> 4) * 8 + (lane & 7));
    const uint32_t b_kb  = (uint32_t)(((lane >> 3) & 1) * 16);
    uint32_t abase[4], am[4], bbase[4], bm[4];
    #pragma unroll
    for (int mf = 0; mf < 4; mf++) {
        uint32_t b = (a_row + mf * 16) * 128;
        abase[mf] = b;
        am[mf] = (b >> 3) & 0x70;
    }
    #pragma unroll
    for (int nfp = 0; nfp < 4; nfp++) {
        uint32_t b = (b_row + nfp * 16) * 128;
        bbase[nfp] = 16384 + b;
        bm[nfp] = (b >> 3) & 0x70;
    }

    load_stage(sb, 0, 0, m0, cb0, tid);
    load_stage(sb, 1, 1, m0, cb0, tid);

    for (int kc = 0; kc < NKC; kc++) {
        if (kc == NKC - 1) CP_WAIT0(); else CP_WAIT1();
        __syncthreads();
        if (kc + 2 < NKC) load_stage(sb, (kc + 2) % NSTG, kc + 2, m0, cb0, tid);

        uint32_t stg = sb + OFF_STG + (kc % NSTG) * STG_BYTES;

        #pragma unroll
        for (int ks = 0; ks < 4; ks++) {            // 32 int8 per ks
            const uint32_t ka = (uint32_t)(ks * 32) + a_kb;
            const uint32_t kb = (uint32_t)(ks * 32) + b_kb;
            uint32_t a0[4][4], b0[8][2];
            #pragma unroll
            for (int mf = 0; mf < 4; mf++)
                ldsm_x4(a0[mf], stg + abase[mf] + (ka ^ am[mf]));
            #pragma unroll
            for (int nfp = 0; nfp < 4; nfp++)
                ldsm_x4(&b0[nfp * 2][0], stg + bbase[nfp] + (kb ^ bm[nfp]));
            #pragma unroll
            for (int mf = 0; mf < 4; mf++)
                #pragma unroll
                for (int nf = 0; nf < 8; nf++)
                    imma(acc[mf][nf], a0[mf], b0[nf]);
        }
    }
    __syncthreads();   // done with stage buffers before smem reuse below

    // ---- epilogue: top-2 over each warp's 64-col group per row ----
    float v1[8], v2[8];
    int   i1[8], i2[8];
    #pragma unroll
    for (int i = 0; i < 8; i++) {
        v1[i] = -3.4e38f; v2[i] = -3.4e38f; i1[i] = 0x7FFFFFF; i2[i] = 0x7FFFFFF;
    }
    float axv[2][4];
    #pragma unroll
    for (int mf = 0; mf < 4; mf++) {
        axv[0][mf] = sax[warp_m * 64 + mf * 16 + (lane >> 2)];
        axv[1][mf] = sax[warp_m * 64 + mf * 16 + (lane >> 2) + 8];
    }

    #pragma unroll
    for (int mf = 0; mf < 4; mf++) {
        #pragma unroll
        for (int nf = 0; nf < 8; nf++) {
            int colb = warp_n * 64 + nf * 8 + (lane & 3) * 2;
            float ae0 = sae[colb], ae1 = sae[colb + 1];
            float q0 = ses[colb], q1 = ses[colb + 1];
            float s0 = axv[0][mf] * ae0 * (float)acc[mf][nf][0] - q0;
            float s1 = axv[0][mf] * ae1 * (float)acc[mf][nf][1] - q1;
            float s2 = axv[1][mf] * ae0 * (float)acc[mf][nf][2] - q0;
            float s3 = axv[1][mf] * ae1 * (float)acc[mf][nf][3] - q1;
            int sl0 = mf * 2, sl1 = mf * 2 + 1;
            upd2(s0, colb,     v1[sl0], i1[sl0], v2[sl0], i2[sl0]);
            upd2(s1, colb + 1, v1[sl0], i1[sl0], v2[sl0], i2[sl0]);
            upd2(s2, colb,     v1[sl1], i1[sl1], v2[sl1], i2[sl1]);
            upd2(s3, colb + 1, v1[sl1], i1[sl1], v2[sl1], i2[sl1]);
        }
    }
    #pragma unroll
    for (int off = 1; off <= 2; off <<= 1) {
        #pragma unroll
        for (int i = 0; i < 8; i++) {
            float ov1 = __shfl_xor_sync(0xFFFFFFFFu, v1[i], off);
            int   oi1 = __shfl_xor_sync(0xFFFFFFFFu, i1[i], off);
            float ov2 = __shfl_xor_sync(0xFFFFFFFFu, v2[i], off);
            int   oi2 = __shfl_xor_sync(0xFFFFFFFFu, i2[i], off);
            upd2(ov1, oi1, v1[i], i1[i], v2[i], i2[i]);
            upd2(ov2, oi2, v1[i], i1[i], v2[i], i2[i]);
        }
    }
    float* rv1 = reinterpret_cast<float*>(smem + OFF_RED);
    int*   ri1 = reinterpret_cast<int*>(smem + OFF_RED + 2048);
    float* rv2 = reinterpret_cast<float*>(smem + OFF_RED + 4096);
    int*   ri2 = reinterpret_cast<int*>(smem + OFF_RED + 6144);
    if ((lane & 3) == 0) {
        #pragma unroll
        for (int i = 0; i < 8; i++) {
            int row = warp_m * 64 + (i >> 1) * 16 + (lane >> 2) + (i & 1) * 8;
            rv1[row * 4 + warp_n] = v1[i];
            ri1[row * 4 + warp_n] = i1[i];
            rv2[row * 4 + warp_n] = v2[i];
            ri2[row * 4 + warp_n] = i2[i];
        }
    }
    __syncthreads();
    // each warp_n slice IS one 64-col group -> write top-2 directly
    #pragma unroll
    for (int i = 0; i < 2; i++) {
        int idx = tid + i * 256;              // 0..511
        int row = idx >> 2;
        int g = idx & 3;
        g_cand[(blockIdx.y * 4 + g) * NQ + m0 + row] =
            make_float4(rv1[row * 4 + g], __int_as_float(cb0 + ri1[row * 4 + g]),
                        rv2[row * 4 + g], __int_as_float(cb0 + ri2[row * 4 + g]));
    }
}

// ---------------------------------------------------------------------------
// Kernel 3: filter candidates, fp64-rescore ambiguous rows, gather output.
// ---------------------------------------------------------------------------
__global__ __launch_bounds__(256)
void finalize_kernel(const float* __restrict__ X, const float* __restrict__ E,
                     float* __restrict__ out, int write_idx) {
    int row = blockIdx.x;
    int t = threadIdx.x;
    __shared__ float4 ent[NGRP];
    __shared__ int    cidx[2 * NGRP];
    __shared__ double csc[2 * NGRP];
    __shared__ int    s_cnt, s_win;

    if (t < NGRP) ent[t] = g_cand[t * NQ + row];
    __syncthreads();

    if (t == 0) {
        float M = -3.4e38f;
        for (int c = 0; c < NGRP; c++) M = fmaxf(M, ent[c].x);
        float thr = M - DELTA;
        int cnt = 0;
        for (int c = 0; c < NGRP; c++) {
            if (ent[c].x >= thr) cidx[cnt++] = __float_as_int(ent[c].y);
            if (ent[c].z >= thr) cidx[cnt++] = __float_as_int(ent[c].w);
        }
        s_cnt = cnt;
        if (cnt == 1) s_win = cidx[0];
    }
    __syncthreads();

    int cnt = s_cnt;
    if (cnt > 1) {
        int wid = t >> 5, lane = t & 31;
        for (int c = wid; c < cnt; c += 8) {
            const float* xr = X + (size_t)row * DD;
            const float* er = E + (size_t)cidx[c] * DD;
            double xe = 0.0, ee = 0.0;
            #pragma unroll
            for (int q = 0; q < DD / 32; q++) {
                double xv = (double)xr[q * 32 + lane];
                double ev = (double)er[q * 32 + lane];
                xe += xv * ev;
                ee += ev * ev;
            }
            double sc = 2.0 * xe - ee;
            #pragma unroll
            for (int o = 16; o; o >>= 1) sc += __shfl_down_sync(0xFFFFFFFFu, sc, o);
            if (lane == 0) csc[c] = sc;
        }
        __syncthreads();
        if (t == 0) {
            double bv = csc[0];
            int bi = cidx[0];
            for (int c = 1; c < cnt; c++) {
                if (csc[c] > bv || (csc[c] == bv && cidx[c] < bi)) {
                    bv = csc[c]; bi = cidx[c];
                }
            }
            s_win = bi;
        }
        __syncthreads();
    }

    int idx = s_win;
    if (t == 0 && write_idx) out[(size_t)NQ * DD + row] = (float)idx;
    if (t < 128) {
        float4 v = *reinterpret_cast<const float4*>(E + (size_t)idx * DD + t * 4);
        *reinterpret_cast<float4*>(out + (size_t)row * DD + t * 4) = v;
    }
}

// ---------------------------------------------------------------------------
extern "C" void kernel_launch(void* const* d_in, const int* in_sizes, int n_in,
                              void* d_out, int out_size) {
    const float* X = (const float*)d_in[0];
    const float* E = (const float*)d_in[1];
    float* out = (float*)d_out;

    static int attr_done = 0;
    if (!attr_done) {
        cudaFuncSetAttribute(vq_mma_kernel,
                             cudaFuncAttributeMaxDynamicSharedMemorySize, SMEM_TOTAL);
        attr_done = 1;
    }

    convert_kernel<<<NQ, 128>>>(X, E);
    vq_mma_kernel<<<dim3(NQ / BMT, NC / BNT), 256, SMEM_TOTAL>>>();
    int write_idx = (out_size >= NQ * DD + NQ) ? 1 : 0;
    finalize_kernel<<<NQ, 256>>>(X, E, out, write_idx);
}

// round 14
// speedup vs baseline: 1.1445x; 1.1445x over previous
#include <cuda_runtime.h>
#include <cstdint>

// SimpleCodebook VQ, R14: R13 + missing __syncthreads() after smem scale
// init (fixes cross-thread smem race on sax/ses/sae that caused rel_err 0.1).
// int8 IMMA approx pass with FULL-K-resident A tile; 4 double-buffered B
// tiles per CTA; top-2 per (row, 32-col group); DELTA=8; fp64 rescore.

#define NQ 8192
#define NC 8192
#define DD 512
#define BMT 128             // CTA tile M
#define TILE_N 128          // codes per B tile
#define NTILES 4            // B tiles per CTA -> 512 codes
#define CODES_CTA (TILE_N * NTILES)
#define NKS 16              // k-batches of 32 over K=512
#define NGRP (NC / 32)      // 256 candidate groups per row (32 cols each)
#define DELTA 8.0f

// smem layout
#define OFF_ESQ 0                   // 512 floats
#define OFF_AE  2048                // 512 floats
#define OFF_AX  4096                // 128 floats
#define OFF_A   8192                // 64KB: 4 chunks x (128 rows x 128B)
#define OFF_B   73728               // 2 bufs x 64KB
#define SMEM_TOTAL 204800           // 200KB -> 1 CTA/SM

// ---- device global scratch ----
__device__ uint8_t g_Xq[NQ * DD];
__device__ uint8_t g_Eq[NC * DD];
__device__ float   g_ax[NQ];        // 2 * max|x_row| / 127
__device__ float   g_ae[NC];        // max|e_row| / 127
__device__ float   g_esq[NC];
__device__ float4  g_cand[NGRP * NQ];   // (v1, idx1_bits, v2, idx2_bits)

static __device__ __forceinline__ uint32_t smem_u32(const void* p) {
    uint32_t a;
    asm("{ .reg .u64 t; cvta.to.shared.u64 t, %1; cvt.u32.u64 %0, t; }" : "=r"(a) : "l"(p));
    return a;
}
static __device__ __forceinline__ uint32_t swz(uint32_t o) { return o ^ ((o >> 3) & 0x70); }

static __device__ __forceinline__ void cp16(uint32_t dst, const void* src) {
    asm volatile("cp.async.cg.shared.global [%0], [%1], 16;" :: "r"(dst), "l"(src) : "memory");
}
#define CP_COMMIT() asm volatile("cp.async.commit_group;" ::: "memory")
#define CP_WAIT0()  asm volatile("cp.async.wait_group 0;" ::: "memory")
#define CP_WAIT1()  asm volatile("cp.async.wait_group 1;" ::: "memory")

static __device__ __forceinline__ void ldsm_x4(uint32_t* r, uint32_t addr) {
    asm volatile("ldmatrix.sync.aligned.m8n8.x4.shared.b16 {%0,%1,%2,%3}, [%4];"
                 : "=r"(r[0]), "=r"(r[1]), "=r"(r[2]), "=r"(r[3]) : "r"(addr));
}
static __device__ __forceinline__ void imma(int* c, const uint32_t* a, const uint32_t* b) {
    asm volatile(
        "mma.sync.aligned.m16n8k32.row.col.s32.s8.s8.s32 "
        "{%0,%1,%2,%3}, {%4,%5,%6,%7}, {%8,%9}, {%0,%1,%2,%3};"
        : "+r"(c[0]), "+r"(c[1]), "+r"(c[2]), "+r"(c[3])
        : "r"(a[0]), "r"(a[1]), "r"(a[2]), "r"(a[3]), "r"(b[0]), "r"(b[1]));
}

static __device__ __forceinline__ int q8(float v, float inv) {
    int q = __float2int_rn(v * inv);
    return max(-127, min(127, q));
}

// ---------------------------------------------------------------------------
// Kernel 1: per-row quantize X (x2 folded into ax) and E; esq = ||e||^2
// ---------------------------------------------------------------------------
__global__ void convert_kernel(const float* __restrict__ X, const float* __restrict__ E) {
    int row = blockIdx.x;
    int t = threadIdx.x;                     // 128
    size_t base = (size_t)row * DD + t * 4;
    __shared__ float wmx[4], wme[4], wsq[4];
    __shared__ float s_ix, s_ie;

    float4 vx = *reinterpret_cast<const float4*>(X + base);
    float4 ve = *reinterpret_cast<const float4*>(E + base);

    float mx = fmaxf(fmaxf(fabsf(vx.x), fabsf(vx.y)), fmaxf(fabsf(vx.z), fabsf(vx.w)));
    float me = fmaxf(fmaxf(fabsf(ve.x), fabsf(ve.y)), fmaxf(fabsf(ve.z), fabsf(ve.w)));
    float sq = ve.x * ve.x + ve.y * ve.y + ve.z * ve.z + ve.w * ve.w;
    #pragma unroll
    for (int o = 16; o; o >>= 1) {
        mx = fmaxf(mx, __shfl_xor_sync(0xFFFFFFFFu, mx, o));
        me = fmaxf(me, __shfl_xor_sync(0xFFFFFFFFu, me, o));
        sq += __shfl_down_sync(0xFFFFFFFFu, sq, o);
    }
    if ((t & 31) == 0) { wmx[t >> 5] = mx; wme[t >> 5] = me; wsq[t >> 5] = sq; }
    __syncthreads();
    if (t == 0) {
        float Mx = fmaxf(fmaxf(wmx[0], wmx[1]), fmaxf(wmx[2], wmx[3]));
        float Me = fmaxf(fmaxf(wme[0], wme[1]), fmaxf(wme[2], wme[3]));
        Mx = fmaxf(Mx, 1e-20f);
        Me = fmaxf(Me, 1e-20f);
        g_ax[row] = 2.0f * Mx / 127.0f;
        g_ae[row] = Me / 127.0f;
        g_esq[row] = wsq[0] + wsq[1] + wsq[2] + wsq[3];
        s_ix = 127.0f / Mx;
        s_ie = 127.0f / Me;
    }
    __syncthreads();
    float ix = s_ix, ie = s_ie;

    uint32_t px = (uint32_t)(q8(vx.x, ix) & 0xFF)
                | ((uint32_t)(q8(vx.y, ix) & 0xFF) << 8)
                | ((uint32_t)(q8(vx.z, ix) & 0xFF) << 16)
                | ((uint32_t)(q8(vx.w, ix) & 0xFF) << 24);
    uint32_t pe = (uint32_t)(q8(ve.x, ie) & 0xFF)
                | ((uint32_t)(q8(ve.y, ie) & 0xFF) << 8)
                | ((uint32_t)(q8(ve.z, ie) & 0xFF) << 16)
                | ((uint32_t)(q8(ve.w, ie) & 0xFF) << 24);
    *reinterpret_cast<uint32_t*>(g_Xq + base) = px;
    *reinterpret_cast<uint32_t*>(g_Eq + base) = pe;
}

// ---------------------------------------------------------------------------
// Kernel 2: IMMA GEMM, A full-K resident, 4 B tiles per CTA.
//           grid (64, 16), 256 threads, 1 CTA/SM.
// ---------------------------------------------------------------------------
static __device__ __forceinline__ void load_A(uint32_t sb, int m0, int tid) {
    #pragma unroll
    for (int c = 0; c < 4; c++) {
        #pragma unroll
        for (int i = 0; i < 4; i++) {
            int cid = tid + i * 256;              // 0..1023
            int row = cid >> 3;
            int c16 = cid & 7;
            const uint8_t* src = g_Xq + (size_t)(m0 + row) * DD + c * 128 + c16 * 16;
            cp16(sb + OFF_A + c * 16384 + swz((uint32_t)(row * 128 + c16 * 16)), src);
        }
    }
}
static __device__ __forceinline__ void load_B(uint32_t sb, int buf, int code0, int tid) {
    #pragma unroll
    for (int c = 0; c < 4; c++) {
        #pragma unroll
        for (int i = 0; i < 4; i++) {
            int cid = tid + i * 256;
            int row = cid >> 3;
            int c16 = cid & 7;
            const uint8_t* src = g_Eq + (size_t)(code0 + row) * DD + c * 128 + c16 * 16;
            cp16(sb + OFF_B + buf * 65536 + c * 16384 +
                 swz((uint32_t)(row * 128 + c16 * 16)), src);
        }
    }
}

static __device__ __forceinline__ void upd2(float v, int i, float& v1, int& i1,
                                            float& v2, int& i2) {
    if (v > v1 || (v == v1 && i < i1)) {
        v2 = v1; i2 = i1; v1 = v; i1 = i;
    } else if (v > v2 || (v == v2 && i < i2)) {
        v2 = v; i2 = i;
    }
}

__global__ __launch_bounds__(256, 1)
void vq_mma_kernel() {
    extern __shared__ char smem[];
    const uint32_t sb = smem_u32(smem);
    const int tid = threadIdx.x;
    const int lane = tid & 31;
    const int wid = tid >> 5;
    const int warp_m = wid >> 2;         // 0..1  (64 rows each)
    const int warp_n = wid & 3;          // 0..3  (32 cols each)
    const int m0 = blockIdx.x * BMT;
    const int cb0 = blockIdx.y * CODES_CTA;

    float* ses = reinterpret_cast<float*>(smem + OFF_ESQ);
    float* sae = reinterpret_cast<float*>(smem + OFF_AE);
    float* sax = reinterpret_cast<float*>(smem + OFF_AX);
    for (int i = tid; i < CODES_CTA; i += 256) {
        ses[i] = g_esq[cb0 + i];
        sae[i] = g_ae[cb0 + i];
    }
    if (tid < BMT) sax[tid] = g_ax[m0 + tid];
    __syncthreads();   // R14 FIX: scales must be visible before any thread
                       // reads sax below (R13 raced here -> rel_err 0.1)

    // prologue: A + B0 (group0), B1 (group1)
    load_A(sb, m0, tid);
    load_B(sb, 0, cb0, tid);
    CP_COMMIT();
    load_B(sb, 1, cb0 + TILE_N, tid);
    CP_COMMIT();

    // ldsm addressing (hoisted swizzle; chunk base added per ks)
    const uint32_t a_row = (uint32_t)(warp_m * 64 + (lane & 15));
    const uint32_t a_kb  = (uint32_t)((lane >> 4) * 16);
    const uint32_t b_row = (uint32_t)(warp_n * 32 + (lane >> 4) * 8 + (lane & 7));
    const uint32_t b_kb  = (uint32_t)(((lane >> 3) & 1) * 16);
    uint32_t abase[4], am[4], bbase[2], bm[2];
    #pragma unroll
    for (int mf = 0; mf < 4; mf++) {
        uint32_t b = (a_row + mf * 16) * 128;
        abase[mf] = b;
        am[mf] = (b >> 3) & 0x70;
    }
    #pragma unroll
    for (int nfp = 0; nfp < 2; nfp++) {
        uint32_t b = (b_row + nfp * 16) * 128;
        bbase[nfp] = b;
        bm[nfp] = (b >> 3) & 0x70;
    }

    int acc[4][4][4];
    #pragma unroll
    for (int mf = 0; mf < 4; mf++)
        #pragma unroll
        for (int nf = 0; nf < 4; nf++)
            #pragma unroll
            for (int c = 0; c < 4; c++) acc[mf][nf][c] = 0;

    float axv0[4], axv1[4];
    #pragma unroll
    for (int mf = 0; mf < 4; mf++) {
        axv0[mf] = sax[warp_m * 64 + mf * 16 + (lane >> 2)];
        axv1[mf] = sax[warp_m * 64 + mf * 16 + (lane >> 2) + 8];
    }

    uint32_t af[2][4][4], bf[2][4][2];

    for (int t = 0; t < NTILES; t++) {
        if (t == NTILES - 1) CP_WAIT0(); else CP_WAIT1();
        __syncthreads();

        const uint32_t Ab = sb + OFF_A;
        const uint32_t Bb = sb + OFF_B + (t & 1) * 65536;

        // preload fragments for ks = 0
        {
            #pragma unroll
            for (int mf = 0; mf < 4; mf++)
                ldsm_x4(af[0][mf], Ab + abase[mf] + (a_kb ^ am[mf]));
            #pragma unroll
            for (int nfp = 0; nfp < 2; nfp++)
                ldsm_x4(&bf[0][nfp * 2][0], Bb + bbase[nfp] + (b_kb ^ bm[nfp]));
        }

        #pragma unroll
        for (int ks = 0; ks < NKS; ks++) {
            const int cur = ks & 1;
            if (ks + 1 < NKS) {                 // prefetch ks+1 fragments
                const int nxt = cur ^ 1;
                const uint32_t ch = (uint32_t)(((ks + 1) >> 2) * 16384);
                const uint32_t ka = (uint32_t)(((ks + 1) & 3) * 32) + a_kb;
                const uint32_t kb = (uint32_t)(((ks + 1) & 3) * 32) + b_kb;
                #pragma unroll
                for (int mf = 0; mf < 4; mf++)
                    ldsm_x4(af[nxt][mf], Ab + ch + abase[mf] + (ka ^ am[mf]));
                #pragma unroll
                for (int nfp = 0; nfp < 2; nfp++)
                    ldsm_x4(&bf[nxt][nfp * 2][0], Bb + ch + bbase[nfp] + (kb ^ bm[nfp]));
            }
            #pragma unroll
            for (int mf = 0; mf < 4; mf++)
                #pragma unroll
                for (int nf = 0; nf < 4; nf++)
                    imma(acc[mf][nf], af[cur][mf], bf[cur][nf]);
        }

        // ---- per-tile epilogue: top-2 over warp's 32 cols per row ----
        {
            float v1[8], v2[8];
            int   i1[8], i2[8];
            #pragma unroll
            for (int i = 0; i < 8; i++) {
                v1[i] = -3.4e38f; v2[i] = -3.4e38f;
                i1[i] = 0x7FFFFFF; i2[i] = 0x7FFFFFF;
            }
            #pragma unroll
            for (int mf = 0; mf < 4; mf++) {
                #pragma unroll
                for (int nf = 0; nf < 4; nf++) {
                    int colb = warp_n * 32 + nf * 8 + (lane & 3) * 2;   // in tile
                    int cidx = t * TILE_N + colb;                        // in CTA slice
                    float ae0 = sae[cidx], ae1 = sae[cidx + 1];
                    float q0 = ses[cidx], q1 = ses[cidx + 1];
                    float s0 = axv0[mf] * ae0 * (float)acc[mf][nf][0] - q0;
                    float s1 = axv0[mf] * ae1 * (float)acc[mf][nf][1] - q1;
                    float s2 = axv1[mf] * ae0 * (float)acc[mf][nf][2] - q0;
                    float s3 = axv1[mf] * ae1 * (float)acc[mf][nf][3] - q1;
                    int sl0 = mf * 2, sl1 = mf * 2 + 1;
                    upd2(s0, colb,     v1[sl0], i1[sl0], v2[sl0], i2[sl0]);
                    upd2(s1, colb + 1, v1[sl0], i1[sl0], v2[sl0], i2[sl0]);
                    upd2(s2, colb,     v1[sl1], i1[sl1], v2[sl1], i2[sl1]);
                    upd2(s3, colb + 1, v1[sl1], i1[sl1], v2[sl1], i2[sl1]);
                }
            }
            #pragma unroll
            for (int off = 1; off <= 2; off <<= 1) {
                #pragma unroll
                for (int i = 0; i < 8; i++) {
                    float ov1 = __shfl_xor_sync(0xFFFFFFFFu, v1[i], off);
                    int   oi1 = __shfl_xor_sync(0xFFFFFFFFu, i1[i], off);
                    float ov2 = __shfl_xor_sync(0xFFFFFFFFu, v2[i], off);
                    int   oi2 = __shfl_xor_sync(0xFFFFFFFFu, i2[i], off);
                    upd2(ov1, oi1, v1[i], i1[i], v2[i], i2[i]);
                    upd2(ov2, oi2, v1[i], i1[i], v2[i], i2[i]);
                }
            }
            if ((lane & 3) == 0) {
                int gidx = blockIdx.y * 16 + t * 4 + warp_n;     // 32-col group
                int code_base = cb0 + t * TILE_N;
                #pragma unroll
                for (int i = 0; i < 8; i++) {
                    int row = warp_m * 64 + (i >> 1) * 16 + (lane >> 2) + (i & 1) * 8;
                    g_cand[(size_t)gidx * NQ + m0 + row] =
                        make_float4(v1[i], __int_as_float(code_base + i1[i]),
                                    v2[i], __int_as_float(code_base + i2[i]));
                }
            }
        }

        // re-zero accumulators for next tile
        #pragma unroll
        for (int mf = 0; mf < 4; mf++)
            #pragma unroll
            for (int nf = 0; nf < 4; nf++)
                #pragma unroll
                for (int c = 0; c < 4; c++) acc[mf][nf][c] = 0;

        __syncthreads();                     // all warps done reading buf t&1
        if (t + 2 < NTILES) {
            load_B(sb, t & 1, cb0 + (t + 2) * TILE_N, tid);
            CP_COMMIT();
        }
    }
}

// ---------------------------------------------------------------------------
// Kernel 3: filter candidates, fp64-rescore ambiguous rows, gather output.
//   one block (256 thr) per row; NGRP = 256 -> fully parallel scan
// ---------------------------------------------------------------------------
__global__ __launch_bounds__(256)
void finalize_kernel(const float* __restrict__ X, const float* __restrict__ E,
                     float* __restrict__ out, int write_idx) {
    int row = blockIdx.x;
    int t = threadIdx.x;
    __shared__ float  wmax[8];
    __shared__ int    cidx[2 * NGRP];
    __shared__ double csc[2 * NGRP];
    __shared__ int    s_cnt, s_win;

    float4 ent = g_cand[(size_t)t * NQ + row];   // t < 256 == NGRP

    // parallel max of ent.x
    float m = ent.x;
    #pragma unroll
    for (int o = 16; o; o >>= 1) m = fmaxf(m, __shfl_xor_sync(0xFFFFFFFFu, m, o));
    if ((t & 31) == 0) wmax[t >> 5] = m;
    if (t == 0) s_cnt = 0;
    __syncthreads();
    float M = wmax[0];
    #pragma unroll
    for (int w = 1; w < 8; w++) M = fmaxf(M, wmax[w]);
    float thr = M - DELTA;

    if (ent.x >= thr) {
        int pos = atomicAdd(&s_cnt, 1);
        cidx[pos] = __float_as_int(ent.y);
    }
    if (ent.z >= thr) {
        int pos = atomicAdd(&s_cnt, 1);
        cidx[pos] = __float_as_int(ent.w);
    }
    __syncthreads();

    int cnt = s_cnt;
    if (cnt == 1) {
        if (t == 0) s_win = cidx[0];
    } else {
        // exact fp64 rescore of each candidate: 2*x.e - ||e||^2
        int wd = t >> 5, lane = t & 31;
        for (int c = wd; c < cnt; c += 8) {
            const float* xr = X + (size_t)row * DD;
            const float* er = E + (size_t)cidx[c] * DD;
            double xe = 0.0, ee = 0.0;
            #pragma unroll
            for (int q = 0; q < DD / 32; q++) {
                double xv = (double)xr[q * 32 + lane];
                double ev = (double)er[q * 32 + lane];
                xe += xv * ev;
                ee += ev * ev;
            }
            double sc = 2.0 * xe - ee;
            #pragma unroll
            for (int o = 16; o; o >>= 1) sc += __shfl_down_sync(0xFFFFFFFFu, sc, o);
            if (lane == 0) csc[c] = sc;
        }
        __syncthreads();
        if (t == 0) {
            double bv = csc[0];
            int bi = cidx[0];
            for (int c = 1; c < cnt; c++) {
                if (csc[c] > bv || (csc[c] == bv && cidx[c] < bi)) {
                    bv = csc[c]; bi = cidx[c];
                }
            }
            s_win = bi;
        }
    }
    __syncthreads();

    int idx = s_win;
    if (t == 0 && write_idx) out[(size_t)NQ * DD + row] = (float)idx;
    if (t < 128) {
        float4 v = *reinterpret_cast<const float4*>(E + (size_t)idx * DD + t * 4);
        *reinterpret_cast<float4*>(out + (size_t)row * DD + t * 4) = v;
    }
}

// ---------------------------------------------------------------------------
extern "C" void kernel_launch(void* const* d_in, const int* in_sizes, int n_in,
                              void* d_out, int out_size) {
    const float* X = (const float*)d_in[0];
    const float* E = (const float*)d_in[1];
    float* out = (float*)d_out;

    static int attr_done = 0;
    if (!attr_done) {
        cudaFuncSetAttribute(vq_mma_kernel,
                             cudaFuncAttributeMaxDynamicSharedMemorySize, SMEM_TOTAL);
        attr_done = 1;
    }

    convert_kernel<<<NQ, 128>>>(X, E);
    vq_mma_kernel<<<dim3(NQ / BMT, NC / CODES_CTA), 256, SMEM_TOTAL>>>();
    int write_idx = (out_size >= NQ * DD + NQ) ? 1 : 0;
    finalize_kernel<<<NQ, 256>>>(X, E, out, write_idx);
}

// round 15
// speedup vs baseline: 1.7273x; 1.5092x over previous
#include <cuda_runtime.h>
#include <cstdint>

// SimpleCodebook VQ, R15: int8 IMMA approx pass; A tile (128x512) resident in
// smem, 2 B tiles of 128 codes per CTA via 16KB double-buffered kc-ring;
// 2 CTAs/SM.  g_cand transposed to [row][grp] for coalesced finalize.
// Top-2 per (row, 32-col group), DELTA=8, fp64 rescore of ambiguous rows.

#define NQ 8192
#define NC 8192
#define DD 512
#define BMT 128             // CTA tile M
#define TILE_N 128          // codes per B tile
#define NTILES 2            // B tiles per CTA -> 256 codes
#define CODES_CTA (TILE_N * NTILES)
#define NUNITS (NTILES * 4) // 8 kc-units (4 kc per tile)
#define NGRP (NC / 32)      // 256 candidate groups per row (32 cols each)
#define DELTA 8.0f

// smem layout
#define OFF_ESQ 0                   // 256 floats
#define OFF_AE  1024                // 256 floats
#define OFF_AX  2048                // 128 floats
#define OFF_A   3072                // 64KB: 4 kc chunks x (128 rows x 128B)
#define OFF_B   68608               // 2 bufs x 16KB
#define SMEM_TOTAL 101376           // 99KB -> 2 CTAs/SM

// ---- device global scratch ----
__device__ uint8_t g_Xq[NQ * DD];
__device__ uint8_t g_Eq[NC * DD];
__device__ float   g_ax[NQ];        // 2 * max|x_row| / 127
__device__ float   g_ae[NC];        // max|e_row| / 127
__device__ float   g_esq[NC];
__device__ float4  g_cand[(size_t)NQ * NGRP];   // [row][grp]

static __device__ __forceinline__ uint32_t smem_u32(const void* p) {
    uint32_t a;
    asm("{ .reg .u64 t; cvta.to.shared.u64 t, %1; cvt.u32.u64 %0, t; }" : "=r"(a) : "l"(p));
    return a;
}
static __device__ __forceinline__ uint32_t swz(uint32_t o) { return o ^ ((o >> 3) & 0x70); }

static __device__ __forceinline__ void cp16(uint32_t dst, const void* src) {
    asm volatile("cp.async.cg.shared.global [%0], [%1], 16;" :: "r"(dst), "l"(src) : "memory");
}
#define CP_COMMIT() asm volatile("cp.async.commit_group;" ::: "memory")
#define CP_WAIT0()  asm volatile("cp.async.wait_group 0;" ::: "memory")
#define CP_WAIT1()  asm volatile("cp.async.wait_group 1;" ::: "memory")

static __device__ __forceinline__ void ldsm_x4(uint32_t* r, uint32_t addr) {
    asm volatile("ldmatrix.sync.aligned.m8n8.x4.shared.b16 {%0,%1,%2,%3}, [%4];"
                 : "=r"(r[0]), "=r"(r[1]), "=r"(r[2]), "=r"(r[3]) : "r"(addr));
}
static __device__ __forceinline__ void imma(int* c, const uint32_t* a, const uint32_t* b) {
    asm volatile(
        "mma.sync.aligned.m16n8k32.row.col.s32.s8.s8.s32 "
        "{%0,%1,%2,%3}, {%4,%5,%6,%7}, {%8,%9}, {%0,%1,%2,%3};"
        : "+r"(c[0]), "+r"(c[1]), "+r"(c[2]), "+r"(c[3])
        : "r"(a[0]), "r"(a[1]), "r"(a[2]), "r"(a[3]), "r"(b[0]), "r"(b[1]));
}

static __device__ __forceinline__ int q8(float v, float inv) {
    int q = __float2int_rn(v * inv);
    return max(-127, min(127, q));
}

// ---------------------------------------------------------------------------
// Kernel 1: per-row quantize X (x2 folded into ax) and E; esq = ||e||^2
// ---------------------------------------------------------------------------
__global__ void convert_kernel(const float* __restrict__ X, const float* __restrict__ E) {
    int row = blockIdx.x;
    int t = threadIdx.x;                     // 128
    size_t base = (size_t)row * DD + t * 4;
    __shared__ float wmx[4], wme[4], wsq[4];
    __shared__ float s_ix, s_ie;

    float4 vx = *reinterpret_cast<const float4*>(X + base);
    float4 ve = *reinterpret_cast<const float4*>(E + base);

    float mx = fmaxf(fmaxf(fabsf(vx.x), fabsf(vx.y)), fmaxf(fabsf(vx.z), fabsf(vx.w)));
    float me = fmaxf(fmaxf(fabsf(ve.x), fabsf(ve.y)), fmaxf(fabsf(ve.z), fabsf(ve.w)));
    float sq = ve.x * ve.x + ve.y * ve.y + ve.z * ve.z + ve.w * ve.w;
    #pragma unroll
    for (int o = 16; o; o >>= 1) {
        mx = fmaxf(mx, __shfl_xor_sync(0xFFFFFFFFu, mx, o));
        me = fmaxf(me, __shfl_xor_sync(0xFFFFFFFFu, me, o));
        sq += __shfl_down_sync(0xFFFFFFFFu, sq, o);
    }
    if ((t & 31) == 0) { wmx[t >> 5] = mx; wme[t >> 5] = me; wsq[t >> 5] = sq; }
    __syncthreads();
    if (t == 0) {
        float Mx = fmaxf(fmaxf(wmx[0], wmx[1]), fmaxf(wmx[2], wmx[3]));
        float Me = fmaxf(fmaxf(wme[0], wme[1]), fmaxf(wme[2], wme[3]));
        Mx = fmaxf(Mx, 1e-20f);
        Me = fmaxf(Me, 1e-20f);
        g_ax[row] = 2.0f * Mx / 127.0f;
        g_ae[row] = Me / 127.0f;
        g_esq[row] = wsq[0] + wsq[1] + wsq[2] + wsq[3];
        s_ix = 127.0f / Mx;
        s_ie = 127.0f / Me;
    }
    __syncthreads();
    float ix = s_ix, ie = s_ie;

    uint32_t px = (uint32_t)(q8(vx.x, ix) & 0xFF)
                | ((uint32_t)(q8(vx.y, ix) & 0xFF) << 8)
                | ((uint32_t)(q8(vx.z, ix) & 0xFF) << 16)
                | ((uint32_t)(q8(vx.w, ix) & 0xFF) << 24);
    uint32_t pe = (uint32_t)(q8(ve.x, ie) & 0xFF)
                | ((uint32_t)(q8(ve.y, ie) & 0xFF) << 8)
                | ((uint32_t)(q8(ve.z, ie) & 0xFF) << 16)
                | ((uint32_t)(q8(ve.w, ie) & 0xFF) << 24);
    *reinterpret_cast<uint32_t*>(g_Xq + base) = px;
    *reinterpret_cast<uint32_t*>(g_Eq + base) = pe;
}

// ---------------------------------------------------------------------------
// Kernel 2: IMMA GEMM, A full-K resident, 2 B tiles per CTA, 2 CTAs/SM.
//           grid (64, 32), 256 threads.
// ---------------------------------------------------------------------------
static __device__ __forceinline__ void load_A(uint32_t sb, int m0, int tid) {
    #pragma unroll
    for (int c = 0; c < 4; c++) {
        #pragma unroll
        for (int i = 0; i < 4; i++) {
            int cid = tid + i * 256;              // 0..1023
            int row = cid >> 3;
            int c16 = cid & 7;
            const uint8_t* src = g_Xq + (size_t)(m0 + row) * DD + c * 128 + c16 * 16;
            cp16(sb + OFF_A + c * 16384 + swz((uint32_t)(row * 128 + c16 * 16)), src);
        }
    }
}
// one kc-chunk of one B tile (128 rows x 128B)
static __device__ __forceinline__ void load_B_unit(uint32_t sb, int buf, int code0,
                                                   int kc, int tid) {
    #pragma unroll
    for (int i = 0; i < 4; i++) {
        int cid = tid + i * 256;
        int row = cid >> 3;
        int c16 = cid & 7;
        const uint8_t* src = g_Eq + (size_t)(code0 + row) * DD + kc * 128 + c16 * 16;
        cp16(sb + OFF_B + buf * 16384 + swz((uint32_t)(row * 128 + c16 * 16)), src);
    }
}

static __device__ __forceinline__ void upd2(float v, int i, float& v1, int& i1,
                                            float& v2, int& i2) {
    if (v > v1 || (v == v1 && i < i1)) {
        v2 = v1; i2 = i1; v1 = v; i1 = i;
    } else if (v > v2 || (v == v2 && i < i2)) {
        v2 = v; i2 = i;
    }
}

__global__ __launch_bounds__(256, 2)
void vq_mma_kernel() {
    extern __shared__ char smem[];
    const uint32_t sb = smem_u32(smem);
    const int tid = threadIdx.x;
    const int lane = tid & 31;
    const int wid = tid >> 5;
    const int warp_m = wid >> 2;         // 0..1  (64 rows each)
    const int warp_n = wid & 3;          // 0..3  (32 cols each)
    const int m0 = blockIdx.x * BMT;
    const int cb0 = blockIdx.y * CODES_CTA;

    float* ses = reinterpret_cast<float*>(smem + OFF_ESQ);
    float* sae = reinterpret_cast<float*>(smem + OFF_AE);
    float* sax = reinterpret_cast<float*>(smem + OFF_AX);
    if (tid < CODES_CTA) {
        ses[tid] = g_esq[cb0 + tid];
        sae[tid] = g_ae[cb0 + tid];
    }
    if (tid < BMT) sax[tid] = g_ax[m0 + tid];
    __syncthreads();   // scales visible before sax reads below

    // prologue: A + B(unit0) -> group0 ; B(unit1) -> group1
    load_A(sb, m0, tid);
    load_B_unit(sb, 0, cb0, 0, tid);
    CP_COMMIT();
    load_B_unit(sb, 1, cb0, 1, tid);
    CP_COMMIT();

    // ldsm addressing (hoisted swizzle; kc-chunk base added per use)
    const uint32_t a_row = (uint32_t)(warp_m * 64 + (lane & 15));
    const uint32_t a_kb  = (uint32_t)((lane >> 4) * 16);
    const uint32_t b_row = (uint32_t)(warp_n * 32 + (lane >> 4) * 8 + (lane & 7));
    const uint32_t b_kb  = (uint32_t)(((lane >> 3) & 1) * 16);
    uint32_t abase[4], am[4], bbase[2], bm[2];
    #pragma unroll
    for (int mf = 0; mf < 4; mf++) {
        uint32_t b = (a_row + mf * 16) * 128;
        abase[mf] = b;
        am[mf] = (b >> 3) & 0x70;
    }
    #pragma unroll
    for (int nfp = 0; nfp < 2; nfp++) {
        uint32_t b = (b_row + nfp * 16) * 128;
        bbase[nfp] = b;
        bm[nfp] = (b >> 3) & 0x70;
    }

    int acc[4][4][4];
    #pragma unroll
    for (int mf = 0; mf < 4; mf++)
        #pragma unroll
        for (int nf = 0; nf < 4; nf++)
            #pragma unroll
            for (int c = 0; c < 4; c++) acc[mf][nf][c] = 0;

    float axv0[4], axv1[4];
    #pragma unroll
    for (int mf = 0; mf < 4; mf++) {
        axv0[mf] = sax[warp_m * 64 + mf * 16 + (lane >> 2)];
        axv1[mf] = sax[warp_m * 64 + mf * 16 + (lane >> 2) + 8];
    }

    uint32_t af[2][4][4], bf[2][4][2];

    for (int u = 0; u < NUNITS; u++) {        // unit u: tile t=u>>2, kc=u&3
        const int t = u >> 2, kc = u & 3;
        if (u == NUNITS - 1) CP_WAIT0(); else CP_WAIT1();
        __syncthreads();

        const uint32_t Ab = sb + OFF_A + (uint32_t)(kc * 16384);
        const uint32_t Bb = sb + OFF_B + (uint32_t)((u & 1) * 16384);

        // preload fragments for ks = 0
        #pragma unroll
        for (int mf = 0; mf < 4; mf++)
            ldsm_x4(af[0][mf], Ab + abase[mf] + (a_kb ^ am[mf]));
        #pragma unroll
        for (int nfp = 0; nfp < 2; nfp++)
            ldsm_x4(&bf[0][nfp * 2][0], Bb + bbase[nfp] + (b_kb ^ bm[nfp]));

        #pragma unroll
        for (int ks = 0; ks < 4; ks++) {
            const int cur = ks & 1;
            if (ks < 3) {                      // prefetch ks+1 fragments
                const int nxt = cur ^ 1;
                const uint32_t ka = (uint32_t)((ks + 1) * 32) + a_kb;
                const uint32_t kb = (uint32_t)((ks + 1) * 32) + b_kb;
                #pragma unroll
                for (int mf = 0; mf < 4; mf++)
                    ldsm_x4(af[nxt][mf], Ab + abase[mf] + (ka ^ am[mf]));
                #pragma unroll
                for (int nfp = 0; nfp < 2; nfp++)
                    ldsm_x4(&bf[nxt][nfp * 2][0], Bb + bbase[nfp] + (kb ^ bm[nfp]));
            }
            #pragma unroll
            for (int mf = 0; mf < 4; mf++)
                #pragma unroll
                for (int nf = 0; nf < 4; nf++)
                    imma(acc[mf][nf], af[cur][mf], bf[cur][nf]);
        }

        if (kc == 3) {
            // ---- tile epilogue: top-2 over warp's 32 cols per row ----
            float v1[8], v2[8];
            int   i1[8], i2[8];
            #pragma unroll
            for (int i = 0; i < 8; i++) {
                v1[i] = -3.4e38f; v2[i] = -3.4e38f;
                i1[i] = 0x7FFFFFF; i2[i] = 0x7FFFFFF;
            }
            #pragma unroll
            for (int mf = 0; mf < 4; mf++) {
                #pragma unroll
                for (int nf = 0; nf < 4; nf++) {
                    int colb = warp_n * 32 + nf * 8 + (lane & 3) * 2;   // in tile
                    int cidx = t * TILE_N + colb;                        // in CTA slice
                    float ae0 = sae[cidx], ae1 = sae[cidx + 1];
                    float q0 = ses[cidx], q1 = ses[cidx + 1];
                    float s0 = axv0[mf] * ae0 * (float)acc[mf][nf][0] - q0;
                    float s1 = axv0[mf] * ae1 * (float)acc[mf][nf][1] - q1;
                    float s2 = axv1[mf] * ae0 * (float)acc[mf][nf][2] - q0;
                    float s3 = axv1[mf] * ae1 * (float)acc[mf][nf][3] - q1;
                    int sl0 = mf * 2, sl1 = mf * 2 + 1;
                    upd2(s0, colb,     v1[sl0], i1[sl0], v2[sl0], i2[sl0]);
                    upd2(s1, colb + 1, v1[sl0], i1[sl0], v2[sl0], i2[sl0]);
                    upd2(s2, colb,     v1[sl1], i1[sl1], v2[sl1], i2[sl1]);
                    upd2(s3, colb + 1, v1[sl1], i1[sl1], v2[sl1], i2[sl1]);
                }
            }
            #pragma unroll
            for (int off = 1; off <= 2; off <<= 1) {
                #pragma unroll
                for (int i = 0; i < 8; i++) {
                    float ov1 = __shfl_xor_sync(0xFFFFFFFFu, v1[i], off);
                    int   oi1 = __shfl_xor_sync(0xFFFFFFFFu, i1[i], off);
                    float ov2 = __shfl_xor_sync(0xFFFFFFFFu, v2[i], off);
                    int   oi2 = __shfl_xor_sync(0xFFFFFFFFu, i2[i], off);
                    upd2(ov1, oi1, v1[i], i1[i], v2[i], i2[i]);
                    upd2(ov2, oi2, v1[i], i1[i], v2[i], i2[i]);
                }
            }
            if ((lane & 3) == 0) {
                int gidx = blockIdx.y * 8 + t * 4 + warp_n;   // 32-col group
                int code_base = cb0 + t * TILE_N;
                #pragma unroll
                for (int i = 0; i < 8; i++) {
                    int row = warp_m * 64 + (i >> 1) * 16 + (lane >> 2) + (i & 1) * 8;
                    g_cand[(size_t)(m0 + row) * NGRP + gidx] =
                        make_float4(v1[i], __int_as_float(code_base + i1[i]),
                                    v2[i], __int_as_float(code_base + i2[i]));
                }
            }
            // re-zero accumulators for next tile
            #pragma unroll
            for (int mf = 0; mf < 4; mf++)
                #pragma unroll
                for (int nf = 0; nf < 4; nf++)
                    #pragma unroll
                    for (int c = 0; c < 4; c++) acc[mf][nf][c] = 0;
        }

        if (u + 2 < NUNITS) {
            __syncthreads();                 // all warps done reading buf u&1
            const int u2 = u + 2;
            load_B_unit(sb, u & 1, cb0 + (u2 >> 2) * TILE_N, u2 & 3, tid);
            CP_COMMIT();
        }
    }
}

// ---------------------------------------------------------------------------
// Kernel 3: filter candidates, fp64-rescore ambiguous rows, gather output.
//   one block (256 thr) per row; coalesced g_cand reads ([row][grp]).
// ---------------------------------------------------------------------------
__global__ __launch_bounds__(256)
void finalize_kernel(const float* __restrict__ X, const float* __restrict__ E,
                     float* __restrict__ out, int write_idx) {
    int row = blockIdx.x;
    int t = threadIdx.x;
    __shared__ float  wmax[8];
    __shared__ int    cidx[2 * NGRP];
    __shared__ double csc[2 * NGRP];
    __shared__ int    s_cnt, s_win;

    float4 ent = g_cand[(size_t)row * NGRP + t];   // t < 256 == NGRP, coalesced

    float m = ent.x;
    #pragma unroll
    for (int o = 16; o; o >>= 1) m = fmaxf(m, __shfl_xor_sync(0xFFFFFFFFu, m, o));
    if ((t & 31) == 0) wmax[t >> 5] = m;
    if (t == 0) s_cnt = 0;
    __syncthreads();
    float M = wmax[0];
    #pragma unroll
    for (int w = 1; w < 8; w++) M = fmaxf(M, wmax[w]);
    float thr = M - DELTA;

    if (ent.x >= thr) {
        int pos = atomicAdd(&s_cnt, 1);
        cidx[pos] = __float_as_int(ent.y);
    }
    if (ent.z >= thr) {
        int pos = atomicAdd(&s_cnt, 1);
        cidx[pos] = __float_as_int(ent.w);
    }
    __syncthreads();

    int cnt = s_cnt;
    if (cnt == 1) {
        if (t == 0) s_win = cidx[0];
    } else {
        int wd = t >> 5, lane = t & 31;
        for (int c = wd; c < cnt; c += 8) {
            const float* xr = X + (size_t)row * DD;
            const float* er = E + (size_t)cidx[c] * DD;
            double xe = 0.0, ee = 0.0;
            #pragma unroll
            for (int q = 0; q < DD / 32; q++) {
                double xv = (double)xr[q * 32 + lane];
                double ev = (double)er[q * 32 + lane];
                xe += xv * ev;
                ee += ev * ev;
            }
            double sc = 2.0 * xe - ee;
            #pragma unroll
            for (int o = 16; o; o >>= 1) sc += __shfl_down_sync(0xFFFFFFFFu, sc, o);
            if (lane == 0) csc[c] = sc;
        }
        __syncthreads();
        if (t == 0) {
            double bv = csc[0];
            int bi = cidx[0];
            for (int c = 1; c < cnt; c++) {
                if (csc[c] > bv || (csc[c] == bv && cidx[c] < bi)) {
                    bv = csc[c]; bi = cidx[c];
                }
            }
            s_win = bi;
        }
    }
    __syncthreads();

    int idx = s_win;
    if (t == 0 && write_idx) out[(size_t)NQ * DD + row] = (float)idx;
    if (t < 128) {
        float4 v = *reinterpret_cast<const float4*>(E + (size_t)idx * DD + t * 4);
        *reinterpret_cast<float4*>(out + (size_t)row * DD + t * 4) = v;
    }
}

// ---------------------------------------------------------------------------
extern "C" void kernel_launch(void* const* d_in, const int* in_sizes, int n_in,
                              void* d_out, int out_size) {
    const float* X = (const float*)d_in[0];
    const float* E = (const float*)d_in[1];
    float* out = (float*)d_out;

    static int attr_done = 0;
    if (!attr_done) {
        cudaFuncSetAttribute(vq_mma_kernel,
                             cudaFuncAttributeMaxDynamicSharedMemorySize, SMEM_TOTAL);
        attr_done = 1;
    }

    convert_kernel<<<NQ, 128>>>(X, E);
    vq_mma_kernel<<<dim3(NQ / BMT, NC / CODES_CTA), 256, SMEM_TOTAL>>>();
    int write_idx = (out_size >= NQ * DD + NQ) ? 1 : 0;
    finalize_kernel<<<NQ, 256>>>(X, E, out, write_idx);
}

// round 16
// speedup vs baseline: 1.7346x; 1.0042x over previous
#include <cuda_runtime.h>
#include <cstdint>

// SimpleCodebook VQ, R16: R15 with register budget fit under the 128-reg
// ceiling (A fragments ping-ponged, B single-buffered) so ptxas keeps the
// software pipeline instead of spilling.  A tile (128x512) smem-resident,
// 2 B tiles per CTA via 16KB double-buffered kc-ring, 2 CTAs/SM.
// Top-2 per (row, 32-col group), DELTA=8, fp64 rescore of ambiguous rows.

#define NQ 8192
#define NC 8192
#define DD 512
#define BMT 128             // CTA tile M
#define TILE_N 128          // codes per B tile
#define NTILES 2            // B tiles per CTA -> 256 codes
#define CODES_CTA (TILE_N * NTILES)
#define NUNITS (NTILES * 4) // 8 kc-units (4 kc per tile)
#define NGRP (NC / 32)      // 256 candidate groups per row (32 cols each)
#define DELTA 8.0f

// smem layout
#define OFF_ESQ 0                   // 256 floats
#define OFF_AE  1024                // 256 floats
#define OFF_AX  2048                // 128 floats
#define OFF_A   3072                // 64KB: 4 kc chunks x (128 rows x 128B)
#define OFF_B   68608               // 2 bufs x 16KB
#define SMEM_TOTAL 101376           // 99KB -> 2 CTAs/SM

// ---- device global scratch ----
__device__ uint8_t g_Xq[NQ * DD];
__device__ uint8_t g_Eq[NC * DD];
__device__ float   g_ax[NQ];        // 2 * max|x_row| / 127
__device__ float   g_ae[NC];        // max|e_row| / 127
__device__ float   g_esq[NC];
__device__ float4  g_cand[(size_t)NQ * NGRP];   // [row][grp]

static __device__ __forceinline__ uint32_t smem_u32(const void* p) {
    uint32_t a;
    asm("{ .reg .u64 t; cvta.to.shared.u64 t, %1; cvt.u32.u64 %0, t; }" : "=r"(a) : "l"(p));
    return a;
}
static __device__ __forceinline__ uint32_t swz(uint32_t o) { return o ^ ((o >> 3) & 0x70); }

static __device__ __forceinline__ void cp16(uint32_t dst, const void* src) {
    asm volatile("cp.async.cg.shared.global [%0], [%1], 16;" :: "r"(dst), "l"(src) : "memory");
}
#define CP_COMMIT() asm volatile("cp.async.commit_group;" ::: "memory")
#define CP_WAIT0()  asm volatile("cp.async.wait_group 0;" ::: "memory")
#define CP_WAIT1()  asm volatile("cp.async.wait_group 1;" ::: "memory")

static __device__ __forceinline__ void ldsm_x4(uint32_t* r, uint32_t addr) {
    asm volatile("ldmatrix.sync.aligned.m8n8.x4.shared.b16 {%0,%1,%2,%3}, [%4];"
                 : "=r"(r[0]), "=r"(r[1]), "=r"(r[2]), "=r"(r[3]) : "r"(addr));
}
static __device__ __forceinline__ void imma(int* c, const uint32_t* a, const uint32_t* b) {
    asm volatile(
        "mma.sync.aligned.m16n8k32.row.col.s32.s8.s8.s32 "
        "{%0,%1,%2,%3}, {%4,%5,%6,%7}, {%8,%9}, {%0,%1,%2,%3};"
        : "+r"(c[0]), "+r"(c[1]), "+r"(c[2]), "+r"(c[3])
        : "r"(a[0]), "r"(a[1]), "r"(a[2]), "r"(a[3]), "r"(b[0]), "r"(b[1]));
}

static __device__ __forceinline__ int q8(float v, float inv) {
    int q = __float2int_rn(v * inv);
    return max(-127, min(127, q));
}

// ---------------------------------------------------------------------------
// Kernel 1: per-row quantize X (x2 folded into ax) and E; esq = ||e||^2
// ---------------------------------------------------------------------------
__global__ void convert_kernel(const float* __restrict__ X, const float* __restrict__ E) {
    int row = blockIdx.x;
    int t = threadIdx.x;                     // 128
    size_t base = (size_t)row * DD + t * 4;
    __shared__ float wmx[4], wme[4], wsq[4];
    __shared__ float s_ix, s_ie;

    float4 vx = *reinterpret_cast<const float4*>(X + base);
    float4 ve = *reinterpret_cast<const float4*>(E + base);

    float mx = fmaxf(fmaxf(fabsf(vx.x), fabsf(vx.y)), fmaxf(fabsf(vx.z), fabsf(vx.w)));
    float me = fmaxf(fmaxf(fabsf(ve.x), fabsf(ve.y)), fmaxf(fabsf(ve.z), fabsf(ve.w)));
    float sq = ve.x * ve.x + ve.y * ve.y + ve.z * ve.z + ve.w * ve.w;
    #pragma unroll
    for (int o = 16; o; o >>= 1) {
        mx = fmaxf(mx, __shfl_xor_sync(0xFFFFFFFFu, mx, o));
        me = fmaxf(me, __shfl_xor_sync(0xFFFFFFFFu, me, o));
        sq += __shfl_down_sync(0xFFFFFFFFu, sq, o);
    }
    if ((t & 31) == 0) { wmx[t >> 5] = mx; wme[t >> 5] = me; wsq[t >> 5] = sq; }
    __syncthreads();
    if (t == 0) {
        float Mx = fmaxf(fmaxf(wmx[0], wmx[1]), fmaxf(wmx[2], wmx[3]));
        float Me = fmaxf(fmaxf(wme[0], wme[1]), fmaxf(wme[2], wme[3]));
        Mx = fmaxf(Mx, 1e-20f);
        Me = fmaxf(Me, 1e-20f);
        g_ax[row] = 2.0f * Mx / 127.0f;
        g_ae[row] = Me / 127.0f;
        g_esq[row] = wsq[0] + wsq[1] + wsq[2] + wsq[3];
        s_ix = 127.0f / Mx;
        s_ie = 127.0f / Me;
    }
    __syncthreads();
    float ix = s_ix, ie = s_ie;

    uint32_t px = (uint32_t)(q8(vx.x, ix) & 0xFF)
                | ((uint32_t)(q8(vx.y, ix) & 0xFF) << 8)
                | ((uint32_t)(q8(vx.z, ix) & 0xFF) << 16)
                | ((uint32_t)(q8(vx.w, ix) & 0xFF) << 24);
    uint32_t pe = (uint32_t)(q8(ve.x, ie) & 0xFF)
                | ((uint32_t)(q8(ve.y, ie) & 0xFF) << 8)
                | ((uint32_t)(q8(ve.z, ie) & 0xFF) << 16)
                | ((uint32_t)(q8(ve.w, ie) & 0xFF) << 24);
    *reinterpret_cast<uint32_t*>(g_Xq + base) = px;
    *reinterpret_cast<uint32_t*>(g_Eq + base) = pe;
}

// ---------------------------------------------------------------------------
// Kernel 2: IMMA GEMM, A full-K resident, 2 B tiles per CTA, 2 CTAs/SM.
//           grid (64, 32), 256 threads.
// ---------------------------------------------------------------------------
static __device__ __forceinline__ void load_A(uint32_t sb, int m0, int tid) {
    #pragma unroll
    for (int c = 0; c < 4; c++) {
        #pragma unroll
        for (int i = 0; i < 4; i++) {
            int cid = tid + i * 256;              // 0..1023
            int row = cid >> 3;
            int c16 = cid & 7;
            const uint8_t* src = g_Xq + (size_t)(m0 + row) * DD + c * 128 + c16 * 16;
            cp16(sb + OFF_A + c * 16384 + swz((uint32_t)(row * 128 + c16 * 16)), src);
        }
    }
}
// one kc-chunk of one B tile (128 rows x 128B)
static __device__ __forceinline__ void load_B_unit(uint32_t sb, int buf, int code0,
                                                   int kc, int tid) {
    #pragma unroll
    for (int i = 0; i < 4; i++) {
        int cid = tid + i * 256;
        int row = cid >> 3;
        int c16 = cid & 7;
        const uint8_t* src = g_Eq + (size_t)(code0 + row) * DD + kc * 128 + c16 * 16;
        cp16(sb + OFF_B + buf * 16384 + swz((uint32_t)(row * 128 + c16 * 16)), src);
    }
}

static __device__ __forceinline__ void upd2(float v, int i, float& v1, int& i1,
                                            float& v2, int& i2) {
    if (v > v1 || (v == v1 && i < i1)) {
        v2 = v1; i2 = i1; v1 = v; i1 = i;
    } else if (v > v2 || (v == v2 && i < i2)) {
        v2 = v; i2 = i;
    }
}

__global__ __launch_bounds__(256, 2)
void vq_mma_kernel() {
    extern __shared__ char smem[];
    const uint32_t sb = smem_u32(smem);
    const int tid = threadIdx.x;
    const int lane = tid & 31;
    const int wid = tid >> 5;
    const int warp_m = wid >> 2;         // 0..1  (64 rows each)
    const int warp_n = wid & 3;          // 0..3  (32 cols each)
    const int m0 = blockIdx.x * BMT;
    const int cb0 = blockIdx.y * CODES_CTA;

    float* ses = reinterpret_cast<float*>(smem + OFF_ESQ);
    float* sae = reinterpret_cast<float*>(smem + OFF_AE);
    float* sax = reinterpret_cast<float*>(smem + OFF_AX);
    if (tid < CODES_CTA) {
        ses[tid] = g_esq[cb0 + tid];
        sae[tid] = g_ae[cb0 + tid];
    }
    if (tid < BMT) sax[tid] = g_ax[m0 + tid];
    __syncthreads();   // scales visible before sax reads below

    // prologue: A + B(unit0) -> group0 ; B(unit1) -> group1
    load_A(sb, m0, tid);
    load_B_unit(sb, 0, cb0, 0, tid);
    CP_COMMIT();
    load_B_unit(sb, 1, cb0, 1, tid);
    CP_COMMIT();

    // ldsm addressing (hoisted swizzle; kc-chunk base added per use)
    const uint32_t a_row = (uint32_t)(warp_m * 64 + (lane & 15));
    const uint32_t a_kb  = (uint32_t)((lane >> 4) * 16);
    const uint32_t b_row = (uint32_t)(warp_n * 32 + (lane >> 4) * 8 + (lane & 7));
    const uint32_t b_kb  = (uint32_t)(((lane >> 3) & 1) * 16);
    uint32_t abase[4], am[4], bbase[2], bm[2];
    #pragma unroll
    for (int mf = 0; mf < 4; mf++) {
        uint32_t b = (a_row + mf * 16) * 128;
        abase[mf] = b;
        am[mf] = (b >> 3) & 0x70;
    }
    #pragma unroll
    for (int nfp = 0; nfp < 2; nfp++) {
        uint32_t b = (b_row + nfp * 16) * 128;
        bbase[nfp] = b;
        bm[nfp] = (b >> 3) & 0x70;
    }

    int acc[4][4][4];
    #pragma unroll
    for (int mf = 0; mf < 4; mf++)
        #pragma unroll
        for (int nf = 0; nf < 4; nf++)
            #pragma unroll
            for (int c = 0; c < 4; c++) acc[mf][nf][c] = 0;

    float axv0[4], axv1[4];
    #pragma unroll
    for (int mf = 0; mf < 4; mf++) {
        axv0[mf] = sax[warp_m * 64 + mf * 16 + (lane >> 2)];
        axv1[mf] = sax[warp_m * 64 + mf * 16 + (lane >> 2) + 8];
    }

    // A fragments ping-ponged (expensive 4-LDSM batches stay pipelined);
    // B fragments single-buffered (2 LDSM exposed per ks; hidden by 4
    // warps/SMSP).  Live set ~126 regs -> fits the 128-reg ceiling.
    uint32_t af[2][4][4], bf[4][2];

    for (int u = 0; u < NUNITS; u++) {        // unit u: tile t=u>>2, kc=u&3
        const int t = u >> 2, kc = u & 3;
        if (u == NUNITS - 1) CP_WAIT0(); else CP_WAIT1();
        __syncthreads();

        const uint32_t Ab = sb + OFF_A + (uint32_t)(kc * 16384);
        const uint32_t Bb = sb + OFF_B + (uint32_t)((u & 1) * 16384);

        // preload A fragments for ks = 0
        #pragma unroll
        for (int mf = 0; mf < 4; mf++)
            ldsm_x4(af[0][mf], Ab + abase[mf] + (a_kb ^ am[mf]));

        #pragma unroll
        for (int ks = 0; ks < 4; ks++) {
            const int cur = ks & 1;
            // load B for this ks (single buffer)
            {
                const uint32_t kb = (uint32_t)(ks * 32) + b_kb;
                #pragma unroll
                for (int nfp = 0; nfp < 2; nfp++)
                    ldsm_x4(&bf[nfp * 2][0], Bb + bbase[nfp] + (kb ^ bm[nfp]));
            }
            // prefetch A for ks+1 (overlaps the IMMA block below)
            if (ks < 3) {
                const int nxt = cur ^ 1;
                const uint32_t ka = (uint32_t)((ks + 1) * 32) + a_kb;
                #pragma unroll
                for (int mf = 0; mf < 4; mf++)
                    ldsm_x4(af[nxt][mf], Ab + abase[mf] + (ka ^ am[mf]));
            }
            #pragma unroll
            for (int mf = 0; mf < 4; mf++)
                #pragma unroll
                for (int nf = 0; nf < 4; nf++)
                    imma(acc[mf][nf], af[cur][mf], bf[nf]);
        }

        if (kc == 3) {
            // ---- tile epilogue: top-2 over warp's 32 cols per row ----
            float v1[8], v2[8];
            int   i1[8], i2[8];
            #pragma unroll
            for (int i = 0; i < 8; i++) {
                v1[i] = -3.4e38f; v2[i] = -3.4e38f;
                i1[i] = 0x7FFFFFF; i2[i] = 0x7FFFFFF;
            }
            #pragma unroll
            for (int mf = 0; mf < 4; mf++) {
                #pragma unroll
                for (int nf = 0; nf < 4; nf++) {
                    int colb = warp_n * 32 + nf * 8 + (lane & 3) * 2;   // in tile
                    int cidx = t * TILE_N + colb;                        // in CTA slice
                    float ae0 = sae[cidx], ae1 = sae[cidx + 1];
                    float q0 = ses[cidx], q1 = ses[cidx + 1];
                    float s0 = axv0[mf] * ae0 * (float)acc[mf][nf][0] - q0;
                    float s1 = axv0[mf] * ae1 * (float)acc[mf][nf][1] - q1;
                    float s2 = axv1[mf] * ae0 * (float)acc[mf][nf][2] - q0;
                    float s3 = axv1[mf] * ae1 * (float)acc[mf][nf][3] - q1;
                    int sl0 = mf * 2, sl1 = mf * 2 + 1;
                    upd2(s0, colb,     v1[sl0], i1[sl0], v2[sl0], i2[sl0]);
                    upd2(s1, colb + 1, v1[sl0], i1[sl0], v2[sl0], i2[sl0]);
                    upd2(s2, colb,     v1[sl1], i1[sl1], v2[sl1], i2[sl1]);
                    upd2(s3, colb + 1, v1[sl1], i1[sl1], v2[sl1], i2[sl1]);
                }
            }
            #pragma unroll
            for (int off = 1; off <= 2; off <<= 1) {
                #pragma unroll
                for (int i = 0; i < 8; i++) {
                    float ov1 = __shfl_xor_sync(0xFFFFFFFFu, v1[i], off);
                    int   oi1 = __shfl_xor_sync(0xFFFFFFFFu, i1[i], off);
                    float ov2 = __shfl_xor_sync(0xFFFFFFFFu, v2[i], off);
                    int   oi2 = __shfl_xor_sync(0xFFFFFFFFu, i2[i], off);
                    upd2(ov1, oi1, v1[i], i1[i], v2[i], i2[i]);
                    upd2(ov2, oi2, v1[i], i1[i], v2[i], i2[i]);
                }
            }
            if ((lane & 3) == 0) {
                int gidx = blockIdx.y * 8 + t * 4 + warp_n;   // 32-col group
                int code_base = cb0 + t * TILE_N;
                #pragma unroll
                for (int i = 0; i < 8; i++) {
                    int row = warp_m * 64 + (i >> 1) * 16 + (lane >> 2) + (i & 1) * 8;
                    g_cand[(size_t)(m0 + row) * NGRP + gidx] =
                        make_float4(v1[i], __int_as_float(code_base + i1[i]),
                                    v2[i], __int_as_float(code_base + i2[i]));
                }
            }
            // re-zero accumulators for next tile
            #pragma unroll
            for (int mf = 0; mf < 4; mf++)
                #pragma unroll
                for (int nf = 0; nf < 4; nf++)
                    #pragma unroll
                    for (int c = 0; c < 4; c++) acc[mf][nf][c] = 0;
        }

        if (u + 2 < NUNITS) {
            __syncthreads();                 // all warps done reading buf u&1
            const int u2 = u + 2;
            load_B_unit(sb, u & 1, cb0 + (u2 >> 2) * TILE_N, u2 & 3, tid);
            CP_COMMIT();
        }
    }
}

// ---------------------------------------------------------------------------
// Kernel 3: filter candidates, fp64-rescore ambiguous rows, gather output.
//   one block (256 thr) per row; coalesced g_cand reads ([row][grp]).
// ---------------------------------------------------------------------------
__global__ __launch_bounds__(256)
void finalize_kernel(const float* __restrict__ X, const float* __restrict__ E,
                     float* __restrict__ out, int write_idx) {
    int row = blockIdx.x;
    int t = threadIdx.x;
    __shared__ float  wmax[8];
    __shared__ int    cidx[2 * NGRP];
    __shared__ double csc[2 * NGRP];
    __shared__ int    s_cnt, s_win;

    float4 ent = g_cand[(size_t)row * NGRP + t];   // t < 256 == NGRP, coalesced

    float m = ent.x;
    #pragma unroll
    for (int o = 16; o; o >>= 1) m = fmaxf(m, __shfl_xor_sync(0xFFFFFFFFu, m, o));
    if ((t & 31) == 0) wmax[t >> 5] = m;
    if (t == 0) s_cnt = 0;
    __syncthreads();
    float M = wmax[0];
    #pragma unroll
    for (int w = 1; w < 8; w++) M = fmaxf(M, wmax[w]);
    float thr = M - DELTA;

    if (ent.x >= thr) {
        int pos = atomicAdd(&s_cnt, 1);
        cidx[pos] = __float_as_int(ent.y);
    }
    if (ent.z >= thr) {
        int pos = atomicAdd(&s_cnt, 1);
        cidx[pos] = __float_as_int(ent.w);
    }
    __syncthreads();

    int cnt = s_cnt;
    if (cnt == 1) {
        if (t == 0) s_win = cidx[0];
    } else {
        int wd = t >> 5, lane = t & 31;
        for (int c = wd; c < cnt; c += 8) {
            const float* xr = X + (size_t)row * DD;
            const float* er = E + (size_t)cidx[c] * DD;
            double xe = 0.0, ee = 0.0;
            #pragma unroll
            for (int q = 0; q < DD / 32; q++) {
                double xv = (double)xr[q * 32 + lane];
                double ev = (double)er[q * 32 + lane];
                xe += xv * ev;
                ee += ev * ev;
            }
            double sc = 2.0 * xe - ee;
            #pragma unroll
            for (int o = 16; o; o >>= 1) sc += __shfl_down_sync(0xFFFFFFFFu, sc, o);
            if (lane == 0) csc[c] = sc;
        }
        __syncthreads();
        if (t == 0) {
            double bv = csc[0];
            int bi = cidx[0];
            for (int c = 1; c < cnt; c++) {
                if (csc[c] > bv || (csc[c] == bv && cidx[c] < bi)) {
                    bv = csc[c]; bi = cidx[c];
                }
            }
            s_win = bi;
        }
    }
    __syncthreads();

    int idx = s_win;
    if (t == 0 && write_idx) out[(size_t)NQ * DD + row] = (float)idx;
    if (t < 128) {
        float4 v = *reinterpret_cast<const float4*>(E + (size_t)idx * DD + t * 4);
        *reinterpret_cast<float4*>(out + (size_t)row * DD + t * 4) = v;
    }
}

// ---------------------------------------------------------------------------
extern "C" void kernel_launch(void* const* d_in, const int* in_sizes, int n_in,
                              void* d_out, int out_size) {
    const float* X = (const float*)d_in[0];
    const float* E = (const float*)d_in[1];
    float* out = (float*)d_out;

    static int attr_done = 0;
    if (!attr_done) {
        cudaFuncSetAttribute(vq_mma_kernel,
                             cudaFuncAttributeMaxDynamicSharedMemorySize, SMEM_TOTAL);
        attr_done = 1;
    }

    convert_kernel<<<NQ, 128>>>(X, E);
    vq_mma_kernel<<<dim3(NQ / BMT, NC / CODES_CTA), 256, SMEM_TOTAL>>>();
    int write_idx = (out_size >= NQ * DD + NQ) ? 1 : 0;
    finalize_kernel<<<NQ, 256>>>(X, E, out, write_idx);
}